// round 9
// baseline (speedup 1.0000x reference)
#include <cuda_runtime.h>

// RALoss fused: loss = sum_i mean_j 10*exp(-sum_{hw}(amax[i,j,hw]-aorg[i,j,hw]))
// Shapes: (4, 64, 512, 512) fp32 x2, scalar fp32 out.
// R2-style streaming (16384 pair-aligned blocks, 8 front-batched LDG.128,
// no predication) + membar-free acq_rel completion + last-block finalize.
// (Resubmission of R7 — previous round died to a container/infra failure.)

#define L_DIM 4
#define B_DIM 64
#define PAIRS (L_DIM * B_DIM)        // 256
#define HW (512 * 512)               // 262144 elems per (i,j) map
#define BLKS_PER_PAIR 64
#define THREADS 256
#define F4_PER_THREAD 4              // 16 floats/thread/input
// per block: 256 thr * 4 f4 * 4 = 4096 elems; * 64 blocks = 262144 = HW (exact)
#define GRID_TOTAL (PAIRS * BLKS_PER_PAIR)   // 16384 blocks

__device__ float g_partials[GRID_TOTAL];
__device__ unsigned int g_done_count;   // zero-init at load; reset each replay

__global__ __launch_bounds__(THREADS, 8)
void raloss_fused_kernel(const float4* __restrict__ amax,
                         const float4* __restrict__ aorg,
                         float* __restrict__ out) {
    const unsigned int blk  = blockIdx.x;   // 0..63  (chunk within pair)
    const unsigned int pair = blockIdx.y;   // 0..255
    const unsigned int tid  = threadIdx.x;
    const unsigned int warp = tid >> 5;
    const unsigned int lane = tid & 31;

    // float4-unit base: pair*(HW/4) + blk*1024  (fits in u32: < 2^24)
    const unsigned int base = pair * (HW / 4) + blk * (THREADS * F4_PER_THREAD);

    // Front-batched: 8 independent 128-bit LDGs in flight, zero predication.
    float4 ma[F4_PER_THREAD];
    float4 mo[F4_PER_THREAD];
#pragma unroll
    for (int k = 0; k < F4_PER_THREAD; k++) {
        unsigned int idx = base + tid + k * THREADS;
        ma[k] = amax[idx];
        mo[k] = aorg[idx];
    }

    float s = 0.0f;
#pragma unroll
    for (int k = 0; k < F4_PER_THREAD; k++) {
        s += (ma[k].x - mo[k].x) + (ma[k].y - mo[k].y)
           + (ma[k].z - mo[k].z) + (ma[k].w - mo[k].w);
    }

#pragma unroll
    for (int off = 16; off > 0; off >>= 1)
        s += __shfl_xor_sync(0xFFFFFFFFu, s, off);

    __shared__ float warp_sums[THREADS / 32];
    __shared__ bool  s_is_last;
    if (lane == 0) warp_sums[warp] = s;
    __syncthreads();

    if (warp == 0) {
        float v = (lane < (THREADS / 32)) ? warp_sums[lane] : 0.0f;
#pragma unroll
        for (int off = 4; off > 0; off >>= 1)
            v += __shfl_xor_sync(0xFFFFFFFFu, v, off);
        if (lane == 0) {
            g_partials[pair * BLKS_PER_PAIR + blk] = v;
            // Release-atomic publishes the partial; the winner's acquire side
            // makes every released partial visible. No separate MEMBAR.GPU.
            unsigned int old;
            asm volatile("atom.acq_rel.gpu.global.add.u32 %0, [%1], %2;"
                         : "=r"(old)
                         : "l"(&g_done_count), "r"(1u)
                         : "memory");
            s_is_last = (old == (unsigned int)(GRID_TOTAL - 1));
        }
    }
    __syncthreads();

    // ---- Last block finalizes: 16384 partials, all L2-resident ----
    if (s_is_last) {
        // Thread t owns pair t: fixed-order sum of its 64 partials (deterministic).
        // Fully unrolled -> 64 independent L2 loads in flight.
        float d = 0.0f;
#pragma unroll
        for (int k = 0; k < BLKS_PER_PAIR; k++)
            d += __ldcg(&g_partials[tid * BLKS_PER_PAIR + k]);

        // contribution: 10*exp(-d)/64  (sum_i mean_j == sum over 256 pairs / 64)
        float v = 10.0f * expf(-d) * (1.0f / (float)B_DIM);

#pragma unroll
        for (int off = 16; off > 0; off >>= 1)
            v += __shfl_xor_sync(0xFFFFFFFFu, v, off);

        if (lane == 0) warp_sums[warp] = v;
        __syncthreads();

        if (warp == 0) {
            float w = (lane < (THREADS / 32)) ? warp_sums[lane] : 0.0f;
#pragma unroll
            for (int off = 4; off > 0; off >>= 1)
                w += __shfl_xor_sync(0xFFFFFFFFu, w, off);
            if (lane == 0) {
                out[0] = w;
                g_done_count = 0;   // reset for next graph replay
            }
        }
    }
}

extern "C" void kernel_launch(void* const* d_in, const int* in_sizes, int n_in,
                              void* d_out, int out_size) {
    const float4* amax = (const float4*)d_in[0];
    const float4* aorg = (const float4*)d_in[1];
    float* out = (float*)d_out;

    dim3 grid(BLKS_PER_PAIR, PAIRS, 1);
    raloss_fused_kernel<<<grid, THREADS>>>(amax, aorg, out);
}

// round 10
// speedup vs baseline: 1.0778x; 1.0778x over previous
#include <cuda_runtime.h>

// RALoss fused: loss = sum_i mean_j 10*exp(-sum_{hw}(amax[i,j,hw]-aorg[i,j,hw]))
// Shapes: (4, 64, 512, 512) fp32 x2, scalar fp32 out.
// R5 structure (1024 pair-aligned fat blocks, single wave) with deeper MLP:
// launch_bounds(256,7) -> 36-reg budget -> 8 front-batched LDG.128 per iter.

#define L_DIM 4
#define B_DIM 64
#define PAIRS (L_DIM * B_DIM)        // 256
#define HW (512 * 512)               // 262144 elems per (i,j) map
#define PAIR_F4 (HW / 4)             // 65536 float4 per pair
#define BLKS_PER_PAIR 4
#define THREADS 256
#define ITERS 16                     // per iter: 256 thr * 4 f4 = 1024 f4
// per block per input: 16 * 1024 = 16384 f4 = PAIR_F4/4  (exact tiling)
#define GRID_TOTAL (PAIRS * BLKS_PER_PAIR)   // 1024 blocks, single wave @7/SM

__device__ float g_partials[GRID_TOTAL];
__device__ unsigned int g_done_count;   // zero-init at load; reset each replay

__global__ __launch_bounds__(THREADS, 7)
void raloss_fused_kernel(const float4* __restrict__ amax,
                         const float4* __restrict__ aorg,
                         float* __restrict__ out) {
    const unsigned int blk  = blockIdx.x;   // 0..3   (chunk within pair)
    const unsigned int pair = blockIdx.y;   // 0..255
    const unsigned int tid  = threadIdx.x;
    const unsigned int warp = tid >> 5;
    const unsigned int lane = tid & 31;

    // Base in float4 units; both streams share the same offset pattern, so
    // SASS uses two 64-bit base registers + immediate offsets (k*4096 B).
    const unsigned int base = pair * PAIR_F4 + blk * (ITERS * THREADS * 4) / 4 * 4;
    const float4* pa = amax + base + tid;
    const float4* po = aorg + base + tid;

    float acc0 = 0.0f, acc1 = 0.0f, acc2 = 0.0f, acc3 = 0.0f;

#pragma unroll
    for (int it = 0; it < ITERS; it++) {
        // 8 independent 128-bit streaming loads in flight.
        float4 ma0 = __ldcs(pa + 0 * THREADS);
        float4 ma1 = __ldcs(pa + 1 * THREADS);
        float4 ma2 = __ldcs(pa + 2 * THREADS);
        float4 ma3 = __ldcs(pa + 3 * THREADS);
        float4 mo0 = __ldcs(po + 0 * THREADS);
        float4 mo1 = __ldcs(po + 1 * THREADS);
        float4 mo2 = __ldcs(po + 2 * THREADS);
        float4 mo3 = __ldcs(po + 3 * THREADS);

        acc0 += (ma0.x - mo0.x) + (ma0.y - mo0.y) + (ma0.z - mo0.z) + (ma0.w - mo0.w);
        acc1 += (ma1.x - mo1.x) + (ma1.y - mo1.y) + (ma1.z - mo1.z) + (ma1.w - mo1.w);
        acc2 += (ma2.x - mo2.x) + (ma2.y - mo2.y) + (ma2.z - mo2.z) + (ma2.w - mo2.w);
        acc3 += (ma3.x - mo3.x) + (ma3.y - mo3.y) + (ma3.z - mo3.z) + (ma3.w - mo3.w);

        pa += 4 * THREADS;
        po += 4 * THREADS;
    }

    float s = (acc0 + acc1) + (acc2 + acc3);

#pragma unroll
    for (int off = 16; off > 0; off >>= 1)
        s += __shfl_xor_sync(0xFFFFFFFFu, s, off);

    __shared__ float warp_sums[THREADS / 32];
    __shared__ bool  s_is_last;
    if (lane == 0) warp_sums[warp] = s;
    __syncthreads();

    if (warp == 0) {
        float v = (lane < (THREADS / 32)) ? warp_sums[lane] : 0.0f;
#pragma unroll
        for (int off = 4; off > 0; off >>= 1)
            v += __shfl_xor_sync(0xFFFFFFFFu, v, off);
        if (lane == 0) {
            g_partials[pair * BLKS_PER_PAIR + blk] = v;
            // Release publishes the partial; winner's acquire sees all partials.
            unsigned int old;
            asm volatile("atom.acq_rel.gpu.global.add.u32 %0, [%1], %2;"
                         : "=r"(old)
                         : "l"(&g_done_count), "r"(1u)
                         : "memory");
            s_is_last = (old == (unsigned int)(GRID_TOTAL - 1));
        }
    }
    __syncthreads();

    // ---- Last block finalizes: 1024 partials, L2-resident ----
    if (s_is_last) {
        // Thread t owns pair t: fixed-order sum of its 4 partials (deterministic).
        float d = 0.0f;
#pragma unroll
        for (int k = 0; k < BLKS_PER_PAIR; k++)
            d += __ldcg(&g_partials[tid * BLKS_PER_PAIR + k]);

        // contribution: 10*exp(-d)/64  (sum_i mean_j == sum over 256 pairs / 64)
        float v = 10.0f * expf(-d) * (1.0f / (float)B_DIM);

#pragma unroll
        for (int off = 16; off > 0; off >>= 1)
            v += __shfl_xor_sync(0xFFFFFFFFu, v, off);

        if (lane == 0) warp_sums[warp] = v;
        __syncthreads();

        if (warp == 0) {
            float w = (lane < (THREADS / 32)) ? warp_sums[lane] : 0.0f;
#pragma unroll
            for (int off = 4; off > 0; off >>= 1)
                w += __shfl_xor_sync(0xFFFFFFFFu, w, off);
            if (lane == 0) {
                out[0] = w;
                g_done_count = 0;   // reset for next graph replay
            }
        }
    }
}

extern "C" void kernel_launch(void* const* d_in, const int* in_sizes, int n_in,
                              void* d_out, int out_size) {
    const float4* amax = (const float4*)d_in[0];
    const float4* aorg = (const float4*)d_in[1];
    float* out = (float*)d_out;

    dim3 grid(BLKS_PER_PAIR, PAIRS, 1);
    raloss_fused_kernel<<<grid, THREADS>>>(amax, aorg, out);
}

// round 11
// speedup vs baseline: 1.0812x; 1.0032x over previous
#include <cuda_runtime.h>

// RALoss fused: loss = sum_i mean_j 10*exp(-sum_{hw}(amax[i,j,hw]-aorg[i,j,hw]))
// Shapes: (4, 64, 512, 512) fp32 x2, scalar fp32 out.
// Champion structure (1024 pair-aligned blocks, single wave, last-block
// finalize) + ld.global.nc.L2::256B loads: 256B L2 fetch granularity halves
// DRAM request count for dense streaming -> higher DRAM burst efficiency.

#define L_DIM 4
#define B_DIM 64
#define PAIRS (L_DIM * B_DIM)        // 256
#define HW (512 * 512)               // 262144 elems per (i,j) map
#define PAIR_F4 (HW / 4)             // 65536 float4 per pair
#define BLKS_PER_PAIR 4
#define THREADS 256
#define ITERS 16                     // per iter: 256 thr * 4 f4 = 1024 f4
#define GRID_TOTAL (PAIRS * BLKS_PER_PAIR)   // 1024 blocks

__device__ float g_partials[GRID_TOTAL];
__device__ unsigned int g_done_count;   // zero-init at load; reset each replay

// 128-bit non-coherent load with 256B L2 fetch-granularity hint.
__device__ __forceinline__ float4 ldg_nc_256(const float4* p) {
    float4 v;
    asm("ld.global.nc.L2::256B.v4.f32 {%0,%1,%2,%3}, [%4];"
        : "=f"(v.x), "=f"(v.y), "=f"(v.z), "=f"(v.w)
        : "l"(p));
    return v;
}

__global__ __launch_bounds__(THREADS, 7)
void raloss_fused_kernel(const float4* __restrict__ amax,
                         const float4* __restrict__ aorg,
                         float* __restrict__ out) {
    const unsigned int blk  = blockIdx.x;   // 0..3   (chunk within pair)
    const unsigned int pair = blockIdx.y;   // 0..255
    const unsigned int tid  = threadIdx.x;
    const unsigned int warp = tid >> 5;
    const unsigned int lane = tid & 31;

    const unsigned int base = pair * PAIR_F4 + blk * (ITERS * THREADS * 4);
    const float4* pa = amax + base + tid;
    const float4* po = aorg + base + tid;

    float acc0 = 0.0f, acc1 = 0.0f, acc2 = 0.0f, acc3 = 0.0f;

#pragma unroll
    for (int it = 0; it < ITERS; it++) {
        float4 ma0 = ldg_nc_256(pa + 0 * THREADS);
        float4 ma1 = ldg_nc_256(pa + 1 * THREADS);
        float4 ma2 = ldg_nc_256(pa + 2 * THREADS);
        float4 ma3 = ldg_nc_256(pa + 3 * THREADS);
        float4 mo0 = ldg_nc_256(po + 0 * THREADS);
        float4 mo1 = ldg_nc_256(po + 1 * THREADS);
        float4 mo2 = ldg_nc_256(po + 2 * THREADS);
        float4 mo3 = ldg_nc_256(po + 3 * THREADS);

        acc0 += (ma0.x - mo0.x) + (ma0.y - mo0.y) + (ma0.z - mo0.z) + (ma0.w - mo0.w);
        acc1 += (ma1.x - mo1.x) + (ma1.y - mo1.y) + (ma1.z - mo1.z) + (ma1.w - mo1.w);
        acc2 += (ma2.x - mo2.x) + (ma2.y - mo2.y) + (ma2.z - mo2.z) + (ma2.w - mo2.w);
        acc3 += (ma3.x - mo3.x) + (ma3.y - mo3.y) + (ma3.z - mo3.z) + (ma3.w - mo3.w);

        pa += 4 * THREADS;
        po += 4 * THREADS;
    }

    float s = (acc0 + acc1) + (acc2 + acc3);

#pragma unroll
    for (int off = 16; off > 0; off >>= 1)
        s += __shfl_xor_sync(0xFFFFFFFFu, s, off);

    __shared__ float warp_sums[THREADS / 32];
    __shared__ bool  s_is_last;
    if (lane == 0) warp_sums[warp] = s;
    __syncthreads();

    if (warp == 0) {
        float v = (lane < (THREADS / 32)) ? warp_sums[lane] : 0.0f;
#pragma unroll
        for (int off = 4; off > 0; off >>= 1)
            v += __shfl_xor_sync(0xFFFFFFFFu, v, off);
        if (lane == 0) {
            g_partials[pair * BLKS_PER_PAIR + blk] = v;
            // Release publishes the partial; winner's acquire sees all partials.
            unsigned int old;
            asm volatile("atom.acq_rel.gpu.global.add.u32 %0, [%1], %2;"
                         : "=r"(old)
                         : "l"(&g_done_count), "r"(1u)
                         : "memory");
            s_is_last = (old == (unsigned int)(GRID_TOTAL - 1));
        }
    }
    __syncthreads();

    // ---- Last block finalizes: 1024 partials, L2-resident ----
    if (s_is_last) {
        // Thread t owns pair t: fixed-order sum of its 4 partials (deterministic).
        float d = 0.0f;
#pragma unroll
        for (int k = 0; k < BLKS_PER_PAIR; k++)
            d += __ldcg(&g_partials[tid * BLKS_PER_PAIR + k]);

        // contribution: 10*exp(-d)/64  (sum_i mean_j == sum over 256 pairs / 64)
        float v = 10.0f * expf(-d) * (1.0f / (float)B_DIM);

#pragma unroll
        for (int off = 16; off > 0; off >>= 1)
            v += __shfl_xor_sync(0xFFFFFFFFu, v, off);

        if (lane == 0) warp_sums[warp] = v;
        __syncthreads();

        if (warp == 0) {
            float w = (lane < (THREADS / 32)) ? warp_sums[lane] : 0.0f;
#pragma unroll
            for (int off = 4; off > 0; off >>= 1)
                w += __shfl_xor_sync(0xFFFFFFFFu, w, off);
            if (lane == 0) {
                out[0] = w;
                g_done_count = 0;   // reset for next graph replay
            }
        }
    }
}

extern "C" void kernel_launch(void* const* d_in, const int* in_sizes, int n_in,
                              void* d_out, int out_size) {
    const float4* amax = (const float4*)d_in[0];
    const float4* aorg = (const float4*)d_in[1];
    float* out = (float*)d_out;

    dim3 grid(BLKS_PER_PAIR, PAIRS, 1);
    raloss_fused_kernel<<<grid, THREADS>>>(amax, aorg, out);
}